// round 6
// baseline (speedup 1.0000x reference)
#include <cuda_runtime.h>

typedef unsigned long long u64;

#define EPSF 1e-7f
#define P_TOT 900
#define NCH 144
#define COUT 32

// Scratch (no allocations allowed)
static __device__ float g_zz[P_TOT * NCH * COUT];   // [p][n][c]
static __device__ float g_rr[P_TOT * NCH * COUT];   // [p][n][c]

__device__ __forceinline__ u64 pk2(float lo, float hi) {
    u64 r; asm("mov.b64 %0,{%1,%2};" : "=l"(r) : "f"(lo), "f"(hi)); return r;
}
__device__ __forceinline__ void upk2(u64 v, float& lo, float& hi) {
    asm("mov.b64 {%0,%1},%2;" : "=f"(lo), "=f"(hi) : "l"(v));
}
__device__ __forceinline__ u64 fma2(u64 a, u64 b, u64 c) {
    u64 r; asm("fma.rn.f32x2 %0,%1,%2,%3;" : "=l"(r) : "l"(a), "l"(b), "l"(c)); return r;
}
__device__ __forceinline__ u64 mul2(u64 a, u64 b) {
    u64 r; asm("mul.rn.f32x2 %0,%1,%2;" : "=l"(r) : "l"(a), "l"(b)); return r;
}
__device__ __forceinline__ u64 add2(u64 a, u64 b) {
    u64 r; asm("add.rn.f32x2 %0,%1,%2;" : "=l"(r) : "l"(a), "l"(b)); return r;
}

extern __shared__ __align__(16) u64 dsm[];

// CTA = 128 threads = 4 warps = 2 parents; warps split 144 children in halves.
// lane = c. W native layout [n][c][k][j]: dense 2KB warp row per n.
// All vote/stat math in packed f32x2 (j-pairs). A staged broadcast-packed.
__global__ void __launch_bounds__(128, 4) me_kernel(
    const float* __restrict__ pose, const float* __restrict__ W,
    const float* __restrict__ beta_a, const float* __restrict__ beta_v,
    float* __restrict__ out, int mode, float lambd)
{
    u64* sA2 = dsm;                          // [2][144*16] (a,a) packed
    u64* sP  = dsm + 2 * NCH * 16;           // [2][2][s|q][8*32]
    float* sRs = (float*)(sP + 2 * 2 * 2 * 256);  // [2][2][32]

    const int t = threadIdx.x;
    const int lane = t & 31, w = t >> 5;
    const int p0 = blockIdx.x * 2;

    // gather child poses, pre-packed as (a,a)
    for (int idx = t; idx < 2 * NCH * 16; idx += 128) {
        int par = idx / 2304, rem = idx - par * 2304;
        int n = rem >> 4, e = rem & 15;
        int p = p0 + par;
        int pr = p / 30, pcl = p % 30;
        int k = n >> 4, ci = n & 15;
        int q = (pr + k / 3) * 32 + pcl + (k % 3);
        float a = pose[q * 256 + ci * 16 + e];
        sA2[par * 2304 + rem] = pk2(a, a);
    }
    __syncthreads();

    const int par = w >> 1, half = w & 1;
    const int p = p0 + par;
    const int c = lane;
    const float* Wb = W + c * 16;                      // + n*512
    const float* rrb = g_rr + (size_t)p * 4608 + c;    // + n*32
    const ulonglong2* Aq = reinterpret_cast<const ulonglong2*>(sA2 + par * 2304);
    const int n0 = half * 72;

    // ---- M step (packed) ----
    u64 s2[8], q2[8];
#pragma unroll
    for (int r = 0; r < 8; r++) { s2[r] = 0ull; q2[r] = 0ull; }
    float rs = 0.f;

#pragma unroll 2
    for (int nn = 0; nn < 72; nn++) {
        const int n = n0 + nn;
        float rrn = (mode == 0) ? 0.03125f : __ldg(rrb + n * 32);
        u64 rr2 = pk2(rrn, rrn);
        rs += rrn;
        const ulonglong2* Wq = reinterpret_cast<const ulonglong2*>(Wb + n * 512);
        ulonglong2 k0 = Wq[0], k1 = Wq[1], k2 = Wq[2], k3 = Wq[3];
        const ulonglong2* Ar = Aq + n * 8;
#pragma unroll
        for (int i = 0; i < 4; i++) {
            ulonglong2 aA = Ar[i * 2];       // (a_i0,a_i0),(a_i1,a_i1)
            ulonglong2 aB = Ar[i * 2 + 1];   // (a_i2,a_i2),(a_i3,a_i3)
            u64 v01 = fma2(aA.x, k0.x, fma2(aA.y, k1.x, fma2(aB.x, k2.x, mul2(aB.y, k3.x))));
            u64 v23 = fma2(aA.x, k0.y, fma2(aA.y, k1.y, fma2(aB.x, k2.y, mul2(aB.y, k3.y))));
            s2[i*2]   = fma2(rr2, v01, s2[i*2]);
            s2[i*2+1] = fma2(rr2, v23, s2[i*2+1]);
            q2[i*2]   = fma2(rr2, mul2(v01, v01), q2[i*2]);
            q2[i*2+1] = fma2(rr2, mul2(v23, v23), q2[i*2+1]);
        }
    }

    // exchange half-partials
    u64* myP = sP + (par * 2 + half) * 512;
#pragma unroll
    for (int r = 0; r < 8; r++) {
        myP[r * 32 + lane] = s2[r];
        myP[256 + r * 32 + lane] = q2[r];
    }
    sRs[(par * 2 + half) * 32 + lane] = rs;
    __syncthreads();
    const u64* oP = sP + (par * 2 + (1 - half)) * 512;
    const float rs_t = sRs[par * 2 * 32 + lane] + sRs[(par * 2 + 1) * 32 + lane];

    const float inv = 1.f / rs_t;
    u64 nm2[8], y2[8];
    float l = 0.f;
#pragma unroll
    for (int r = 0; r < 8; r++) {
        u64 sc = add2(s2[r], oP[r * 32 + lane]);
        u64 qc = add2(q2[r], oP[256 + r * 32 + lane]);
        float sa, sb, qa, qb;
        upk2(sc, sa, sb); upk2(qc, qa, qb);
        float ma = sa * inv, mb = sb * inv;
        float va = fmaxf(qa * inv - ma * ma, 1e-30f);
        float vb = fmaxf(qb * inv - mb * mb, 1e-30f);
        l += __logf(sqrtf(va) + EPSF) + __logf(sqrtf(vb) + EPSF);
        nm2[r] = pk2(-ma, -mb);
        y2[r]  = pk2(0.5f / va, 0.5f / vb);
    }
    const float cost = 16.f * beta_v[c] + rs_t * l;
    const float act = 1.f / (1.f + __expf(-lambd * (beta_a[c] - cost)));

    if (mode == 2) {
        if (half == 0) {
            out[p * COUT + c] = act;
            float* op = out + 28800 + (size_t)p * 512 + c * 16;
#pragma unroll
            for (int r = 0; r < 8; r++) {
                float ma, mb;
                upk2(nm2[r], ma, mb);
                op[r * 2]     = -ma;
                op[r * 2 + 1] = -mb;
            }
        }
        return;
    }

    // ---- E step (packed, recompute votes) ----
    const float zb = __logf(act + EPSF) - l;
    float* zzb = g_zz + (size_t)p * 4608 + c;
#pragma unroll 2
    for (int nn = 0; nn < 72; nn++) {
        const int n = n0 + nn;
        const ulonglong2* Wq = reinterpret_cast<const ulonglong2*>(Wb + n * 512);
        ulonglong2 k0 = Wq[0], k1 = Wq[1], k2 = Wq[2], k3 = Wq[3];
        const ulonglong2* Ar = Aq + n * 8;
        u64 pe2 = 0ull;
#pragma unroll
        for (int i = 0; i < 4; i++) {
            ulonglong2 aA = Ar[i * 2];
            ulonglong2 aB = Ar[i * 2 + 1];
            u64 v01 = fma2(aA.x, k0.x, fma2(aA.y, k1.x, fma2(aB.x, k2.x, mul2(aB.y, k3.x))));
            u64 v23 = fma2(aA.x, k0.y, fma2(aA.y, k1.y, fma2(aB.x, k2.y, mul2(aB.y, k3.y))));
            u64 d01 = add2(v01, nm2[i*2]);
            u64 d23 = add2(v23, nm2[i*2+1]);
            pe2 = fma2(mul2(d01, d01), y2[i*2], pe2);
            pe2 = fma2(mul2(d23, d23), y2[i*2+1], pe2);
        }
        float pa, pb;
        upk2(pe2, pa, pb);
        zzb[n * 32] = zb - (pa + pb);
    }
}

// Softmax over parent axis p for every (n,c) on layout [p][n][c].
// One block per n (144), 1024 threads = 32 c x 32 p-stripes.
__global__ void __launch_bounds__(1024) softmax_kernel()
{
    __shared__ float red[32 * 33];
    __shared__ float gv[32];
    const int n = blockIdx.x;
    const int t = threadIdx.x;
    const int c = t & 31, st = t >> 5;
    const int base = n * 32 + c;

    float m = -1e30f;
    for (int p = st; p < P_TOT; p += 32)
        m = fmaxf(m, g_zz[(size_t)p * 4608 + base]);
    red[st * 33 + c] = m;
    __syncthreads();
    if (t < 32) {
        float M = red[t];
#pragma unroll
        for (int i = 1; i < 32; i++) M = fmaxf(M, red[i * 33 + t]);
        gv[t] = M;
    }
    __syncthreads();
    const float M = gv[c];

    float s = 0.f;
    for (int p = st; p < P_TOT; p += 32)
        s += __expf(g_zz[(size_t)p * 4608 + base] - M);
    red[st * 33 + c] = s;
    __syncthreads();
    if (t < 32) {
        float S = 0.f;
#pragma unroll
        for (int i = 0; i < 32; i++) S += red[i * 33 + t];
        gv[t] = 1.f / S;
    }
    __syncthreads();
    const float Sinv = gv[c];

    for (int p = st; p < P_TOT; p += 32) {
        size_t idx = (size_t)p * 4608 + base;
        g_rr[idx] = __expf(g_zz[idx] - M) * Sinv;
    }
}

extern "C" void kernel_launch(void* const* d_in, const int* in_sizes, int n_in,
                              void* d_out, int out_size)
{
    const float* pose = (const float*)d_in[1];
    const float* W    = (const float*)d_in[2];
    const float* ba   = (const float*)d_in[3];
    const float* bv   = (const float*)d_in[4];
    float* out = (float*)d_out;

    const size_t shmem = (2 * NCH * 16 + 2 * 2 * 2 * 256) * sizeof(u64)
                       + 128 * sizeof(float);   // 53760 B
    cudaFuncSetAttribute(me_kernel, cudaFuncAttributeMaxDynamicSharedMemorySize,
                         (int)shmem);

    me_kernel<<<450, 128, shmem>>>(pose, W, ba, bv, out, 0, 0.0f);
    softmax_kernel<<<NCH, 1024>>>();
    me_kernel<<<450, 128, shmem>>>(pose, W, ba, bv, out, 1, 0.0005f);
    softmax_kernel<<<NCH, 1024>>>();
    me_kernel<<<450, 128, shmem>>>(pose, W, ba, bv, out, 2, 0.000975f);
}

// round 7
// speedup vs baseline: 1.1041x; 1.1041x over previous
#include <cuda_runtime.h>

#define EPSF 1e-7f
#define P_TOT 900
#define NCH 144
#define COUT 32

// Scratch (no allocations allowed)
static __device__ float g_zz[P_TOT * NCH * COUT];   // [p][n][c]
static __device__ float g_rr[P_TOT * NCH * COUT];   // [p][n][c]

// CTA = 128 threads = 4 warps = 2 parents; warp pair (half 0/1) splits the
// 144 children. lane = c. W native layout [n][c][k][j]: dense 2KB row per n.
// MODE 0: rr uniform (specialized unweighted sums), M+E.
// MODE 1: read rr, M+E.   MODE 2: read rr, M only, write outputs.
template<int MODE>
__global__ void __launch_bounds__(128, 4) me_kernel(
    const float* __restrict__ pose, const float* __restrict__ W,
    const float* __restrict__ beta_a, const float* __restrict__ beta_v,
    float* __restrict__ out, float lambd)
{
    __shared__ float sA[2][NCH * 16];          // child poses per parent
    __shared__ float sPart[2][2][2][512];      // [par][half][s/q][e*32+c]
    __shared__ float sRs[2][2][32];            // [par][half][c]

    const int t = threadIdx.x;
    const int lane = t & 31, w = t >> 5;
    const int p0 = blockIdx.x * 2;

    // gather child poses for both parents (float4, 64B rows)
    for (int idx = t; idx < 2 * NCH * 4; idx += 128) {
        int par = idx / 576, r = idx - par * 576;
        int n = r >> 2, vq = r & 3;
        int p = p0 + par;
        int pr = p / 30, pcl = p % 30;
        int k = n >> 4, ci = n & 15;
        int q = (pr + k / 3) * 32 + pcl + (k % 3);
        float4 val = reinterpret_cast<const float4*>(pose + q * 256 + ci * 16)[vq];
        *reinterpret_cast<float4*>(&sA[par][n * 16 + vq * 4]) = val;
    }
    __syncthreads();

    const int par = w >> 1, half = w & 1;
    const int p = p0 + par;
    const int c = lane;
    const float* Ab = sA[par];
    const float* Wb = W + c * 16;                          // + n*512
    const float* rrb = g_rr + (size_t)p * 4608 + c;        // + n*32
    const int n0 = half * 72;

    // ---- M step: software-pipelined over 72 children ----
    float s[16], q[16];
#pragma unroll
    for (int e = 0; e < 16; e++) { s[e] = 0.f; q[e] = 0.f; }
    float rs = 0.f;

    float4 cw0, cw1, cw2, cw3;
    {
        const float4* q4 = reinterpret_cast<const float4*>(Wb + n0 * 512);
        cw0 = q4[0]; cw1 = q4[1]; cw2 = q4[2]; cw3 = q4[3];
    }
    float crr = (MODE == 0) ? 0.f : __ldg(rrb + n0 * 32);

#pragma unroll 2
    for (int nn = 0; nn < 72; nn++) {
        const int n = n0 + nn;
        const int np = (n + 1 < 144) ? n + 1 : 143;
        const float4* q4n = reinterpret_cast<const float4*>(Wb + np * 512);
        float4 nw0 = q4n[0], nw1 = q4n[1], nw2 = q4n[2], nw3 = q4n[3];
        float nrr = (MODE == 0) ? 0.f : __ldg(rrb + np * 32);

        const float4* Ap = reinterpret_cast<const float4*>(Ab + n * 16);
        if (MODE != 0) rs += crr;
#pragma unroll
        for (int i = 0; i < 4; i++) {
            float4 a = Ap[i];
            float vx = a.x * cw0.x + a.y * cw1.x + a.z * cw2.x + a.w * cw3.x;
            float vy = a.x * cw0.y + a.y * cw1.y + a.z * cw2.y + a.w * cw3.y;
            float vz = a.x * cw0.z + a.y * cw1.z + a.z * cw2.z + a.w * cw3.z;
            float vw = a.x * cw0.w + a.y * cw1.w + a.z * cw2.w + a.w * cw3.w;
            if (MODE == 0) {
                s[i*4+0] += vx; q[i*4+0] += vx * vx;
                s[i*4+1] += vy; q[i*4+1] += vy * vy;
                s[i*4+2] += vz; q[i*4+2] += vz * vz;
                s[i*4+3] += vw; q[i*4+3] += vw * vw;
            } else {
                s[i*4+0] += crr * vx; q[i*4+0] += crr * (vx * vx);
                s[i*4+1] += crr * vy; q[i*4+1] += crr * (vy * vy);
                s[i*4+2] += crr * vz; q[i*4+2] += crr * (vz * vz);
                s[i*4+3] += crr * vw; q[i*4+3] += crr * (vw * vw);
            }
        }
        cw0 = nw0; cw1 = nw1; cw2 = nw2; cw3 = nw3; crr = nrr;
    }

    // exchange partials between the two halves of this parent
#pragma unroll
    for (int e = 0; e < 16; e++) {
        sPart[par][half][0][e * 32 + lane] = s[e];
        sPart[par][half][1][e * 32 + lane] = q[e];
    }
    if (MODE != 0) sRs[par][half][lane] = rs;
    __syncthreads();

    const float rs_t = (MODE == 0) ? 4.5f
                     : (sRs[par][0][lane] + sRs[par][1][lane]);
    const float inv  = (MODE == 0) ? (1.f / 144.f) : (1.f / rs_t);

    float mean[16], i2v[16];
    float l = 0.f;
#pragma unroll
    for (int e = 0; e < 16; e++) {
        float se = sPart[par][0][0][e * 32 + lane] + sPart[par][1][0][e * 32 + lane];
        float qe = sPart[par][0][1][e * 32 + lane] + sPart[par][1][1][e * 32 + lane];
        float m = se * inv;
        mean[e] = m;
        float var = fmaxf(qe * inv - m * m, 1e-30f);
        l += __logf(sqrtf(var) + EPSF);
        i2v[e] = 0.5f / var;
    }
    const float cost = 16.f * beta_v[c] + rs_t * l;
    const float act = 1.f / (1.f + __expf(-lambd * (beta_a[c] - cost)));

    if (MODE == 2) {
        if (half == 0) {
            out[p * COUT + c] = act;
            float4* op = reinterpret_cast<float4*>(out + 28800 + (size_t)p * 512 + c * 16);
#pragma unroll
            for (int i = 0; i < 4; i++) {
                float4 m4 = { mean[i*4+0], mean[i*4+1], mean[i*4+2], mean[i*4+3] };
                op[i] = m4;
            }
        }
        return;
    }

    // ---- E step: recompute votes (pipelined), thread-local pe, direct STG ----
    const float zb = __logf(act + EPSF) - l;
    float* zzb = g_zz + (size_t)p * 4608 + c;

    {
        const float4* q4 = reinterpret_cast<const float4*>(Wb + n0 * 512);
        cw0 = q4[0]; cw1 = q4[1]; cw2 = q4[2]; cw3 = q4[3];
    }
#pragma unroll 2
    for (int nn = 0; nn < 72; nn++) {
        const int n = n0 + nn;
        const int np = (n + 1 < 144) ? n + 1 : 143;
        const float4* q4n = reinterpret_cast<const float4*>(Wb + np * 512);
        float4 nw0 = q4n[0], nw1 = q4n[1], nw2 = q4n[2], nw3 = q4n[3];

        const float4* Ap = reinterpret_cast<const float4*>(Ab + n * 16);
        float pe = 0.f;
#pragma unroll
        for (int i = 0; i < 4; i++) {
            float4 a = Ap[i];
            float vx = a.x * cw0.x + a.y * cw1.x + a.z * cw2.x + a.w * cw3.x;
            float vy = a.x * cw0.y + a.y * cw1.y + a.z * cw2.y + a.w * cw3.y;
            float vz = a.x * cw0.z + a.y * cw1.z + a.z * cw2.z + a.w * cw3.z;
            float vw = a.x * cw0.w + a.y * cw1.w + a.z * cw2.w + a.w * cw3.w;
            float d;
            d = vx - mean[i*4+0]; pe += d * d * i2v[i*4+0];
            d = vy - mean[i*4+1]; pe += d * d * i2v[i*4+1];
            d = vz - mean[i*4+2]; pe += d * d * i2v[i*4+2];
            d = vw - mean[i*4+3]; pe += d * d * i2v[i*4+3];
        }
        zzb[n * 32] = zb - pe;
        cw0 = nw0; cw1 = nw1; cw2 = nw2; cw3 = nw3;
    }
}

// Softmax over parent axis p for every (n,c) on layout [p][n][c].
// One block per n (144), 1024 threads = 32 c x 32 p-stripes.
__global__ void __launch_bounds__(1024) softmax_kernel()
{
    __shared__ float red[32 * 33];
    __shared__ float gv[32];
    const int n = blockIdx.x;
    const int t = threadIdx.x;
    const int c = t & 31, st = t >> 5;
    const int base = n * 32 + c;

    float m = -1e30f;
    for (int p = st; p < P_TOT; p += 32)
        m = fmaxf(m, g_zz[(size_t)p * 4608 + base]);
    red[st * 33 + c] = m;
    __syncthreads();
    if (t < 32) {
        float M = red[t];
#pragma unroll
        for (int i = 1; i < 32; i++) M = fmaxf(M, red[i * 33 + t]);
        gv[t] = M;
    }
    __syncthreads();
    const float M = gv[c];

    float s = 0.f;
    for (int p = st; p < P_TOT; p += 32)
        s += __expf(g_zz[(size_t)p * 4608 + base] - M);
    red[st * 33 + c] = s;
    __syncthreads();
    if (t < 32) {
        float S = 0.f;
#pragma unroll
        for (int i = 0; i < 32; i++) S += red[i * 33 + t];
        gv[t] = 1.f / S;
    }
    __syncthreads();
    const float Sinv = gv[c];

    for (int p = st; p < P_TOT; p += 32) {
        size_t idx = (size_t)p * 4608 + base;
        g_rr[idx] = __expf(g_zz[idx] - M) * Sinv;
    }
}

extern "C" void kernel_launch(void* const* d_in, const int* in_sizes, int n_in,
                              void* d_out, int out_size)
{
    const float* pose = (const float*)d_in[1];
    const float* W    = (const float*)d_in[2];
    const float* ba   = (const float*)d_in[3];
    const float* bv   = (const float*)d_in[4];
    float* out = (float*)d_out;

    me_kernel<0><<<450, 128>>>(pose, W, ba, bv, out, 0.0f);
    softmax_kernel<<<NCH, 1024>>>();
    me_kernel<1><<<450, 128>>>(pose, W, ba, bv, out, 0.0005f);
    softmax_kernel<<<NCH, 1024>>>();
    me_kernel<2><<<450, 128>>>(pose, W, ba, bv, out, 0.000975f);
}

// round 8
// speedup vs baseline: 1.6746x; 1.5167x over previous
#include <cuda_runtime.h>

#define EPSF 1e-7f
#define P_TOT 900
#define NCH 144
#define COUT 32

// Scratch (no allocations allowed)
static __device__ float g_zz[P_TOT * NCH * COUT];   // [p][n][c]
static __device__ float g_rr[P_TOT * NCH * COUT];   // [p][n][c]
static __device__ float g_W4[NCH * COUT * 16];      // [n][k][c][j] coalesced

// W[(n*32+c)*16 + k*4 + j] -> W4[((n*4+k)*32 + c)*4 + j]
__global__ void __launch_bounds__(256) wtrans_kernel(const float* __restrict__ W) {
    int t = blockIdx.x * 256 + threadIdx.x;   // over 144*32*4 float4 rows
    if (t < NCH * COUT * 4) {
        int k = t & 3, c = (t >> 2) & 31, n = t >> 7;
        float4 v = reinterpret_cast<const float4*>(W)[t];
        reinterpret_cast<float4*>(g_W4)[(n * 4 + k) * 32 + c] = v;
    }
}

// CTA = 128 threads = 4 warps = 2 parents; warp pair (half 0/1) splits the
// 144 children. lane = c. W4 layout: per n, each warp issues 4 fully
// coalesced LDG.128 (512B contiguous each).
// MODE 0: rr uniform (unweighted sums), M+E.
// MODE 1: read rr, M+E.   MODE 2: read rr, M only, write outputs.
template<int MODE>
__global__ void __launch_bounds__(128, 4) me_kernel(
    const float* __restrict__ pose,
    const float* __restrict__ beta_a, const float* __restrict__ beta_v,
    float* __restrict__ out, float lambd)
{
    __shared__ float sA[2][NCH * 16];          // child poses per parent
    __shared__ float sPart[2][2][2][512];      // [par][half][s/q][e*32+c]
    __shared__ float sRs[2][2][32];            // [par][half][c]

    const int t = threadIdx.x;
    const int lane = t & 31, w = t >> 5;
    const int p0 = blockIdx.x * 2;

    // gather child poses for both parents (float4, 64B rows)
    for (int idx = t; idx < 2 * NCH * 4; idx += 128) {
        int par = idx / 576, r = idx - par * 576;
        int n = r >> 2, vq = r & 3;
        int p = p0 + par;
        int pr = p / 30, pcl = p % 30;
        int k = n >> 4, ci = n & 15;
        int q = (pr + k / 3) * 32 + pcl + (k % 3);
        float4 val = reinterpret_cast<const float4*>(pose + q * 256 + ci * 16)[vq];
        *reinterpret_cast<float4*>(&sA[par][n * 16 + vq * 4]) = val;
    }
    __syncthreads();

    const int par = w >> 1, half = w & 1;
    const int p = p0 + par;
    const int c = lane;
    const float* Ab = sA[par];
    const float4* W4 = reinterpret_cast<const float4*>(g_W4) + c;   // + n*128 + k*32
    const float* rrb = g_rr + (size_t)p * 4608 + c;                 // + n*32
    const int n0 = half * 72;

    // ---- M step: software-pipelined over 72 children ----
    float s[16], q[16];
#pragma unroll
    for (int e = 0; e < 16; e++) { s[e] = 0.f; q[e] = 0.f; }
    float rs = 0.f;

    float4 cw0, cw1, cw2, cw3;
    {
        const float4* q4 = W4 + n0 * 128;
        cw0 = q4[0]; cw1 = q4[32]; cw2 = q4[64]; cw3 = q4[96];
    }
    float crr = (MODE == 0) ? 0.f : __ldg(rrb + n0 * 32);

#pragma unroll 2
    for (int nn = 0; nn < 72; nn++) {
        const int n = n0 + nn;
        const int np = (n + 1 < 144) ? n + 1 : 143;
        const float4* q4n = W4 + np * 128;
        float4 nw0 = q4n[0], nw1 = q4n[32], nw2 = q4n[64], nw3 = q4n[96];
        float nrr = (MODE == 0) ? 0.f : __ldg(rrb + np * 32);

        const float4* Ap = reinterpret_cast<const float4*>(Ab + n * 16);
        if (MODE != 0) rs += crr;
#pragma unroll
        for (int i = 0; i < 4; i++) {
            float4 a = Ap[i];
            float vx = a.x * cw0.x + a.y * cw1.x + a.z * cw2.x + a.w * cw3.x;
            float vy = a.x * cw0.y + a.y * cw1.y + a.z * cw2.y + a.w * cw3.y;
            float vz = a.x * cw0.z + a.y * cw1.z + a.z * cw2.z + a.w * cw3.z;
            float vw = a.x * cw0.w + a.y * cw1.w + a.z * cw2.w + a.w * cw3.w;
            if (MODE == 0) {
                s[i*4+0] += vx; q[i*4+0] += vx * vx;
                s[i*4+1] += vy; q[i*4+1] += vy * vy;
                s[i*4+2] += vz; q[i*4+2] += vz * vz;
                s[i*4+3] += vw; q[i*4+3] += vw * vw;
            } else {
                s[i*4+0] += crr * vx; q[i*4+0] += crr * (vx * vx);
                s[i*4+1] += crr * vy; q[i*4+1] += crr * (vy * vy);
                s[i*4+2] += crr * vz; q[i*4+2] += crr * (vz * vz);
                s[i*4+3] += crr * vw; q[i*4+3] += crr * (vw * vw);
            }
        }
        cw0 = nw0; cw1 = nw1; cw2 = nw2; cw3 = nw3; crr = nrr;
    }

    // exchange partials between the two halves of this parent
#pragma unroll
    for (int e = 0; e < 16; e++) {
        sPart[par][half][0][e * 32 + lane] = s[e];
        sPart[par][half][1][e * 32 + lane] = q[e];
    }
    if (MODE != 0) sRs[par][half][lane] = rs;
    __syncthreads();

    const float rs_t = (MODE == 0) ? 4.5f
                     : (sRs[par][0][lane] + sRs[par][1][lane]);
    const float inv  = (MODE == 0) ? (1.f / 144.f) : (1.f / rs_t);

    float mean[16], i2v[16];
    float l = 0.f;
#pragma unroll
    for (int e = 0; e < 16; e++) {
        float se = sPart[par][0][0][e * 32 + lane] + sPart[par][1][0][e * 32 + lane];
        float qe = sPart[par][0][1][e * 32 + lane] + sPart[par][1][1][e * 32 + lane];
        float m = se * inv;
        mean[e] = m;
        float var = fmaxf(qe * inv - m * m, 1e-30f);
        l += __logf(sqrtf(var) + EPSF);
        i2v[e] = 0.5f / var;
    }
    const float cost = 16.f * beta_v[c] + rs_t * l;
    const float act = 1.f / (1.f + __expf(-lambd * (beta_a[c] - cost)));

    if (MODE == 2) {
        if (half == 0) {
            out[p * COUT + c] = act;
            float4* op = reinterpret_cast<float4*>(out + 28800 + (size_t)p * 512 + c * 16);
#pragma unroll
            for (int i = 0; i < 4; i++) {
                float4 m4 = { mean[i*4+0], mean[i*4+1], mean[i*4+2], mean[i*4+3] };
                op[i] = m4;
            }
        }
        return;
    }

    // ---- E step: recompute votes (pipelined), thread-local pe, direct STG ----
    const float zb = __logf(act + EPSF) - l;
    float* zzb = g_zz + (size_t)p * 4608 + c;

    {
        const float4* q4 = W4 + n0 * 128;
        cw0 = q4[0]; cw1 = q4[32]; cw2 = q4[64]; cw3 = q4[96];
    }
#pragma unroll 2
    for (int nn = 0; nn < 72; nn++) {
        const int n = n0 + nn;
        const int np = (n + 1 < 144) ? n + 1 : 143;
        const float4* q4n = W4 + np * 128;
        float4 nw0 = q4n[0], nw1 = q4n[32], nw2 = q4n[64], nw3 = q4n[96];

        const float4* Ap = reinterpret_cast<const float4*>(Ab + n * 16);
        float pe = 0.f;
#pragma unroll
        for (int i = 0; i < 4; i++) {
            float4 a = Ap[i];
            float vx = a.x * cw0.x + a.y * cw1.x + a.z * cw2.x + a.w * cw3.x;
            float vy = a.x * cw0.y + a.y * cw1.y + a.z * cw2.y + a.w * cw3.y;
            float vz = a.x * cw0.z + a.y * cw1.z + a.z * cw2.z + a.w * cw3.z;
            float vw = a.x * cw0.w + a.y * cw1.w + a.z * cw2.w + a.w * cw3.w;
            float d;
            d = vx - mean[i*4+0]; pe += d * d * i2v[i*4+0];
            d = vy - mean[i*4+1]; pe += d * d * i2v[i*4+1];
            d = vz - mean[i*4+2]; pe += d * d * i2v[i*4+2];
            d = vw - mean[i*4+3]; pe += d * d * i2v[i*4+3];
        }
        zzb[n * 32] = zb - pe;
        cw0 = nw0; cw1 = nw1; cw2 = nw2; cw3 = nw3;
    }
}

// Softmax over parent axis p for every (n,c) on layout [p][n][c].
// One block per n (144), 1024 threads = 32 c x 32 p-stripes.
__global__ void __launch_bounds__(1024) softmax_kernel()
{
    __shared__ float red[32 * 33];
    __shared__ float gv[32];
    const int n = blockIdx.x;
    const int t = threadIdx.x;
    const int c = t & 31, st = t >> 5;
    const int base = n * 32 + c;

    float m = -1e30f;
    for (int p = st; p < P_TOT; p += 32)
        m = fmaxf(m, g_zz[(size_t)p * 4608 + base]);
    red[st * 33 + c] = m;
    __syncthreads();
    if (t < 32) {
        float M = red[t];
#pragma unroll
        for (int i = 1; i < 32; i++) M = fmaxf(M, red[i * 33 + t]);
        gv[t] = M;
    }
    __syncthreads();
    const float M = gv[c];

    float s = 0.f;
    for (int p = st; p < P_TOT; p += 32)
        s += __expf(g_zz[(size_t)p * 4608 + base] - M);
    red[st * 33 + c] = s;
    __syncthreads();
    if (t < 32) {
        float S = 0.f;
#pragma unroll
        for (int i = 0; i < 32; i++) S += red[i * 33 + t];
        gv[t] = 1.f / S;
    }
    __syncthreads();
    const float Sinv = gv[c];

    for (int p = st; p < P_TOT; p += 32) {
        size_t idx = (size_t)p * 4608 + base;
        g_rr[idx] = __expf(g_zz[idx] - M) * Sinv;
    }
}

extern "C" void kernel_launch(void* const* d_in, const int* in_sizes, int n_in,
                              void* d_out, int out_size)
{
    const float* pose = (const float*)d_in[1];
    const float* W    = (const float*)d_in[2];
    const float* ba   = (const float*)d_in[3];
    const float* bv   = (const float*)d_in[4];
    float* out = (float*)d_out;

    wtrans_kernel<<<72, 256>>>(W);
    me_kernel<0><<<450, 128>>>(pose, ba, bv, out, 0.0f);
    softmax_kernel<<<NCH, 1024>>>();
    me_kernel<1><<<450, 128>>>(pose, ba, bv, out, 0.0005f);
    softmax_kernel<<<NCH, 1024>>>();
    me_kernel<2><<<450, 128>>>(pose, ba, bv, out, 0.000975f);
}

// round 9
// speedup vs baseline: 1.8292x; 1.0923x over previous
#include <cuda_runtime.h>

#define EPSF 1e-7f
#define P_TOT 900
#define NCH 144
#define COUT 32

// Scratch (no allocations allowed)
static __device__ float g_zz[P_TOT * NCH * COUT];   // [p][n][c]
static __device__ float g_rr[P_TOT * NCH * COUT];   // [p][n][c]
static __device__ float g_W4[NCH * COUT * 16];      // [n][k][c][j] coalesced

// W[(n*32+c)*16 + k*4 + j] -> W4[((n*4+k)*32 + c)*4 + j]
__global__ void __launch_bounds__(256) wtrans_kernel(const float* __restrict__ W) {
    int t = blockIdx.x * 256 + threadIdx.x;   // over 144*32*4 float4 rows
    if (t < NCH * COUT * 4) {
        int k = t & 3, c = (t >> 2) & 31, n = t >> 7;
        float4 v = reinterpret_cast<const float4*>(W)[t];
        reinterpret_cast<float4*>(g_W4)[(n * 4 + k) * 32 + c] = v;
    }
}

// CTA = 128 threads = 4 warps = ONE parent; warp w handles children
// n in [36w, 36w+36). lane = c. Per n each warp issues 4 fully coalesced
// LDG.128 (512B contiguous) from W4.
// MODE 0: rr uniform (unweighted sums), M+E.
// MODE 1: read rr, M+E.   MODE 2: read rr, M only, write outputs.
template<int MODE>
__global__ void __launch_bounds__(128, 4) me_kernel(
    const float* __restrict__ pose,
    const float* __restrict__ beta_a, const float* __restrict__ beta_v,
    float* __restrict__ out, float lambd)
{
    __shared__ float sA[NCH * 16];            // child poses
    __shared__ float sPart[4][2][512];        // [warp][s/q][e*32+c]
    __shared__ float sRs[4][32];              // [warp][c]

    const int t = threadIdx.x;
    const int lane = t & 31, w = t >> 5;
    const int p = blockIdx.x;
    const int pr = p / 30, pcl = p % 30;

    // gather child poses (float4, 64B rows)
    for (int idx = t; idx < NCH * 4; idx += 128) {
        int n = idx >> 2, vq = idx & 3;
        int k = n >> 4, ci = n & 15;
        int q = (pr + k / 3) * 32 + pcl + (k % 3);
        float4 val = reinterpret_cast<const float4*>(pose + q * 256 + ci * 16)[vq];
        *reinterpret_cast<float4*>(&sA[n * 16 + vq * 4]) = val;
    }
    __syncthreads();

    const int c = lane;
    const float4* W4 = reinterpret_cast<const float4*>(g_W4) + c;   // + n*128 + k*32
    const float* rrb = g_rr + (size_t)p * 4608 + c;                 // + n*32
    const int n0 = w * 36;

    // ---- M step: software-pipelined over 36 children ----
    float s[16], q[16];
#pragma unroll
    for (int e = 0; e < 16; e++) { s[e] = 0.f; q[e] = 0.f; }
    float rs = 0.f;

    float4 cw0, cw1, cw2, cw3;
    {
        const float4* q4 = W4 + n0 * 128;
        cw0 = q4[0]; cw1 = q4[32]; cw2 = q4[64]; cw3 = q4[96];
    }
    float crr = (MODE == 0) ? 0.f : __ldg(rrb + n0 * 32);

#pragma unroll 2
    for (int nn = 0; nn < 36; nn++) {
        const int n = n0 + nn;
        const int np = (n + 1 < 144) ? n + 1 : 143;
        const float4* q4n = W4 + np * 128;
        float4 nw0 = q4n[0], nw1 = q4n[32], nw2 = q4n[64], nw3 = q4n[96];
        float nrr = (MODE == 0) ? 0.f : __ldg(rrb + np * 32);

        const float4* Ap = reinterpret_cast<const float4*>(sA + n * 16);
        if (MODE != 0) rs += crr;
#pragma unroll
        for (int i = 0; i < 4; i++) {
            float4 a = Ap[i];
            float vx = a.x * cw0.x + a.y * cw1.x + a.z * cw2.x + a.w * cw3.x;
            float vy = a.x * cw0.y + a.y * cw1.y + a.z * cw2.y + a.w * cw3.y;
            float vz = a.x * cw0.z + a.y * cw1.z + a.z * cw2.z + a.w * cw3.z;
            float vw = a.x * cw0.w + a.y * cw1.w + a.z * cw2.w + a.w * cw3.w;
            if (MODE == 0) {
                s[i*4+0] += vx; q[i*4+0] += vx * vx;
                s[i*4+1] += vy; q[i*4+1] += vy * vy;
                s[i*4+2] += vz; q[i*4+2] += vz * vz;
                s[i*4+3] += vw; q[i*4+3] += vw * vw;
            } else {
                s[i*4+0] += crr * vx; q[i*4+0] += crr * (vx * vx);
                s[i*4+1] += crr * vy; q[i*4+1] += crr * (vy * vy);
                s[i*4+2] += crr * vz; q[i*4+2] += crr * (vz * vz);
                s[i*4+3] += crr * vw; q[i*4+3] += crr * (vw * vw);
            }
        }
        cw0 = nw0; cw1 = nw1; cw2 = nw2; cw3 = nw3; crr = nrr;
    }

    // exchange partials among the 4 warps
#pragma unroll
    for (int e = 0; e < 16; e++) {
        sPart[w][0][e * 32 + lane] = s[e];
        sPart[w][1][e * 32 + lane] = q[e];
    }
    if (MODE != 0) sRs[w][lane] = rs;
    __syncthreads();

    const float rs_t = (MODE == 0) ? 4.5f
                     : (sRs[0][lane] + sRs[1][lane] + sRs[2][lane] + sRs[3][lane]);
    const float inv  = (MODE == 0) ? (1.f / 144.f) : (1.f / rs_t);

    float mean[16], i2v[16], t2[16];
    float l = 0.f, Kc = 0.f;
#pragma unroll
    for (int e = 0; e < 16; e++) {
        float se = sPart[0][0][e * 32 + lane] + sPart[1][0][e * 32 + lane]
                 + sPart[2][0][e * 32 + lane] + sPart[3][0][e * 32 + lane];
        float qe = sPart[0][1][e * 32 + lane] + sPart[1][1][e * 32 + lane]
                 + sPart[2][1][e * 32 + lane] + sPart[3][1][e * 32 + lane];
        float m = se * inv;
        mean[e] = m;
        float var = fmaxf(qe * inv - m * m, 1e-30f);
        l += __logf(sqrtf(var) + EPSF);
        float y = 0.5f / var;
        i2v[e] = y;
        t2[e] = -2.f * m * y;
        Kc += m * m * y;
    }
    const float cost = 16.f * beta_v[c] + rs_t * l;
    const float act = 1.f / (1.f + __expf(-lambd * (beta_a[c] - cost)));

    if (MODE == 2) {
        if (w == 0) {
            out[p * COUT + c] = act;
            float4* op = reinterpret_cast<float4*>(out + 28800 + (size_t)p * 512 + c * 16);
#pragma unroll
            for (int i = 0; i < 4; i++) {
                float4 m4 = { mean[i*4+0], mean[i*4+1], mean[i*4+2], mean[i*4+3] };
                op[i] = m4;
            }
        }
        return;
    }

    // ---- E step: recompute votes (pipelined); pe = sum v*(v*y - 2my); zz = zb2 - pe
    const float zb2 = __logf(act + EPSF) - l - Kc;
    float* zzb = g_zz + (size_t)p * 4608 + c;

    {
        const float4* q4 = W4 + n0 * 128;
        cw0 = q4[0]; cw1 = q4[32]; cw2 = q4[64]; cw3 = q4[96];
    }
#pragma unroll 2
    for (int nn = 0; nn < 36; nn++) {
        const int n = n0 + nn;
        const int np = (n + 1 < 144) ? n + 1 : 143;
        const float4* q4n = W4 + np * 128;
        float4 nw0 = q4n[0], nw1 = q4n[32], nw2 = q4n[64], nw3 = q4n[96];

        const float4* Ap = reinterpret_cast<const float4*>(sA + n * 16);
        float pe = 0.f;
#pragma unroll
        for (int i = 0; i < 4; i++) {
            float4 a = Ap[i];
            float vx = a.x * cw0.x + a.y * cw1.x + a.z * cw2.x + a.w * cw3.x;
            float vy = a.x * cw0.y + a.y * cw1.y + a.z * cw2.y + a.w * cw3.y;
            float vz = a.x * cw0.z + a.y * cw1.z + a.z * cw2.z + a.w * cw3.z;
            float vw = a.x * cw0.w + a.y * cw1.w + a.z * cw2.w + a.w * cw3.w;
            pe += vx * fmaf(vx, i2v[i*4+0], t2[i*4+0]);
            pe += vy * fmaf(vy, i2v[i*4+1], t2[i*4+1]);
            pe += vz * fmaf(vz, i2v[i*4+2], t2[i*4+2]);
            pe += vw * fmaf(vw, i2v[i*4+3], t2[i*4+3]);
        }
        zzb[n * 32] = zb2 - pe;
        cw0 = nw0; cw1 = nw1; cw2 = nw2; cw3 = nw3;
    }
}

// Softmax over parent axis p for every (n,c) on layout [p][n][c].
// One block per n (144), 1024 threads = 32 c x 32 p-stripes.
__global__ void __launch_bounds__(1024) softmax_kernel()
{
    __shared__ float red[32 * 33];
    __shared__ float gv[32];
    const int n = blockIdx.x;
    const int t = threadIdx.x;
    const int c = t & 31, st = t >> 5;
    const int base = n * 32 + c;

    float m = -1e30f;
    for (int p = st; p < P_TOT; p += 32)
        m = fmaxf(m, g_zz[(size_t)p * 4608 + base]);
    red[st * 33 + c] = m;
    __syncthreads();
    if (t < 32) {
        float M = red[t];
#pragma unroll
        for (int i = 1; i < 32; i++) M = fmaxf(M, red[i * 33 + t]);
        gv[t] = M;
    }
    __syncthreads();
    const float M = gv[c];

    float s = 0.f;
    for (int p = st; p < P_TOT; p += 32)
        s += __expf(g_zz[(size_t)p * 4608 + base] - M);
    red[st * 33 + c] = s;
    __syncthreads();
    if (t < 32) {
        float S = 0.f;
#pragma unroll
        for (int i = 0; i < 32; i++) S += red[i * 33 + t];
        gv[t] = 1.f / S;
    }
    __syncthreads();
    const float Sinv = gv[c];

    for (int p = st; p < P_TOT; p += 32) {
        size_t idx = (size_t)p * 4608 + base;
        g_rr[idx] = __expf(g_zz[idx] - M) * Sinv;
    }
}

extern "C" void kernel_launch(void* const* d_in, const int* in_sizes, int n_in,
                              void* d_out, int out_size)
{
    const float* pose = (const float*)d_in[1];
    const float* W    = (const float*)d_in[2];
    const float* ba   = (const float*)d_in[3];
    const float* bv   = (const float*)d_in[4];
    float* out = (float*)d_out;

    wtrans_kernel<<<72, 256>>>(W);
    me_kernel<0><<<P_TOT, 128>>>(pose, ba, bv, out, 0.0f);
    softmax_kernel<<<NCH, 1024>>>();
    me_kernel<1><<<P_TOT, 128>>>(pose, ba, bv, out, 0.0005f);
    softmax_kernel<<<NCH, 1024>>>();
    me_kernel<2><<<P_TOT, 128>>>(pose, ba, bv, out, 0.000975f);
}